// round 13
// baseline (speedup 1.0000x reference)
#include <cuda_runtime.h>
#include <cuda_fp16.h>
#include <cstdint>
#include <cstring>
#include <cfloat>

// VectorQuantizer: B=131072, D=64, K=1024, fp32.
// DUAL-PIPE persistent kernel: warps 0-3 score codes [0,704) on the tensor
// pipe (fp16 mma.sync); warps 4-7 score codes [704,1024) on the fma pipe
// (register-microtiled f32x2, fp16 operands cvt'd on load, fp32 accum).
// Pair-compressed top-4 keys, margin certify, parallel exact duel, rare fallback.
// R13: fixes R12's pointer-signedness compile error (unsigned char* -> const unsigned char*).

#define VQ_B 131072
#define VQ_K 1024
#define VQ_D 64
#define ROWS 128
#define THREADS 256
#define NTILES (VQ_B / ROWS)   // 1024
#define GRID_MAIN 148
#define CT 704                 // tensor codes
#define NT_TENSOR (CT / 8)     // 88
#define FC (VQ_K - CT)         // 320 fma codes
#define FCHUNKS (FC / 32)      // 10

__device__ float g_esq[VQ_K];
__device__ int g_emax2_bits = 0;
__device__ int g_flag_count;
__device__ int g_flag_rows[VQ_B];
__device__ __half g_eh[(size_t)VQ_K * VQ_D];   // fp16 e, granule-swizzled (tensor layout)
__device__ __half g_xh[(size_t)VQ_B * VQ_D];   // fp16 x, granule-swizzled
__device__ __half g_et16[VQ_D * FC];           // fp16 e k-major slice, codes [704,1024)

// Dynamic smem layout (bytes)
#define EH_OFF    0         // 704 * 128B = 90112
#define EST_OFF   90112     // 64 * 320 * 2B = 40960 (k-major fp16)
#define XS_OFF    131072    // 2 x-tile fp16 buffers * 16384 = 32768
#define XS32_OFF  163840    // fp32 k-major x tile: 64*128*4 = 32768
#define ESQ_OFF   196608    // 1024 floats = 4096
#define KEYS_OFF  200704    // [2][128] uint4 = 4096
#define XSQ_OFF   204800    // 128 floats = 512
#define DBS_OFF   205312    // 256 floats = 1024
#define DBI_OFF   206336    // 256 ints = 1024
#define WIDX_OFF  207360    // 128 ints = 512
#define SMEM_TOTAL 207872

// ---------------- PTX helpers ----------------
static __device__ __forceinline__ uint32_t smem_u32(const void* p) {
    uint32_t a;
    asm("{ .reg .u64 t; cvta.to.shared.u64 t, %1; cvt.u32.u64 %0, t; }" : "=r"(a) : "l"(p));
    return a;
}
#define CP_ASYNC16(dst, src) \
    asm volatile("cp.async.cg.shared.global [%0], [%1], 16;" :: "r"(dst), "l"(src) : "memory")
#define CP_COMMIT() asm volatile("cp.async.commit_group;" ::: "memory")
#define CP_WAIT0() asm volatile("cp.async.wait_group 0;" ::: "memory")
#define LDSM_X4(r0, r1, r2, r3, a) \
    asm volatile("ldmatrix.sync.aligned.m8n8.x4.shared.b16 {%0,%1,%2,%3}, [%4];" \
                 : "=r"(r0), "=r"(r1), "=r"(r2), "=r"(r3) : "r"(a))
#define MMA16816(c0, c1, c2, c3, a0, a1, a2, a3, b0, b1) \
    asm volatile("mma.sync.aligned.m16n8k16.row.col.f32.f16.f16.f32 " \
                 "{%0,%1,%2,%3}, {%4,%5,%6,%7}, {%8,%9}, {%0,%1,%2,%3};" \
                 : "+f"(c0), "+f"(c1), "+f"(c2), "+f"(c3) \
                 : "r"(a0), "r"(a1), "r"(a2), "r"(a3), "r"(b0), "r"(b1))

// sorted top-4 insert (keys ascending)
#define INS4(k1, k2, k3, k4, u) do { \
    uint32_t _t1 = max(k1, u); k1 = min(k1, u); \
    uint32_t _t2 = max(k2, _t1); k2 = min(k2, _t1); \
    uint32_t _t3 = max(k3, _t2); k3 = min(k3, _t2); \
    k4 = min(k4, _t3); \
} while (0)

// f32x2 packed math
#define FMA_F32X2(acc, a, b) asm("fma.rn.f32x2 %0, %1, %2, %0;" : "+l"(acc) : "l"(a), "l"(b))
#define ADD_F32X2(d, a, b) asm("add.rn.f32x2 %0, %1, %2;" : "=l"(d) : "l"(a), "l"(b))
#define DUP_F32X2(d, s) asm("mov.b64 %0, {%1, %1};" : "=l"(d) : "f"(s))
static __device__ __forceinline__ float2 u64f2(uint64_t u) { float2 v; memcpy(&v, &u, 8); return v; }
static __device__ __forceinline__ uint64_t f2u64(float2 v) { uint64_t u; memcpy(&u, &v, 8); return u; }

// ---------------- prologue 1: x AND e -> fp16 (granule-swizzled) ----------------
__global__ void vq_prep(const float* __restrict__ x, const float* __restrict__ e) {
    int t = blockIdx.x * blockDim.x + threadIdx.x;  // VQ_B*8 threads
    if (t == 0) g_flag_count = 0;
    {   // x: one 8-dim granule of one row
        int r = t >> 3, g = t & 7;
        const float4* p = reinterpret_cast<const float4*>(x + (size_t)r * VQ_D + g * 8);
        float4 v0 = p[0], v1 = p[1];
        __half2 h[4] = {__floats2half2_rn(v0.x, v0.y), __floats2half2_rn(v0.z, v0.w),
                        __floats2half2_rn(v1.x, v1.y), __floats2half2_rn(v1.z, v1.w)};
        uint4 pk;
        memcpy(&pk, h, 16);
        int gp = g ^ (r & 7);
        *reinterpret_cast<uint4*>(&g_xh[(size_t)r * VQ_D + gp * 8]) = pk;
    }
    if (t < VQ_K) {  // e row + esq
        int c = t;
        const float4* row = reinterpret_cast<const float4*>(e + (size_t)c * VQ_D);
        float s = 0.f;
#pragma unroll
        for (int g = 0; g < 8; g++) {
            float4 v0 = row[2 * g], v1 = row[2 * g + 1];
            s += v0.x * v0.x + v0.y * v0.y + v0.z * v0.z + v0.w * v0.w;
            s += v1.x * v1.x + v1.y * v1.y + v1.z * v1.z + v1.w * v1.w;
            __half2 h[4] = {__floats2half2_rn(v0.x, v0.y), __floats2half2_rn(v0.z, v0.w),
                            __floats2half2_rn(v1.x, v1.y), __floats2half2_rn(v1.z, v1.w)};
            uint4 pk;
            memcpy(&pk, h, 16);
            int gp = g ^ (c & 7);
            *reinterpret_cast<uint4*>(&g_eh[(size_t)c * VQ_D + gp * 8]) = pk;
        }
        g_esq[c] = s;
        atomicMax(&g_emax2_bits, __float_as_int(s));
    }
}

// ---------------- prologue 2: fma-slice e -> fp16 k-major ----------------
__global__ void vq_prep_et(const float* __restrict__ e) {
    int idx = blockIdx.x * blockDim.x + threadIdx.x;  // 64*320 = 20480
    if (idx >= VQ_D * FC) return;
    int k = idx / FC, c = idx - k * FC;
    g_et16[idx] = __float2half_rn(e[(size_t)(CT + c) * VQ_D + k]);
}

// exact fp32 score with 4 split accumulators
static __device__ __forceinline__ float exact_score(const float4* xr, const float* e, int code,
                                                    float esq) {
    const float4* er = reinterpret_cast<const float4*>(e + (size_t)code * VQ_D);
    float a0 = 0.f, a1 = 0.f, a2 = 0.f, a3 = 0.f;
#pragma unroll
    for (int i = 0; i < 16; i += 4) {
        float4 xa = xr[i], ba = er[i];
        float4 xb = xr[i + 1], bb = er[i + 1];
        float4 xc = xr[i + 2], bc = er[i + 2];
        float4 xd = xr[i + 3], bd = er[i + 3];
        a0 = fmaf(xa.x, ba.x, a0); a0 = fmaf(xa.y, ba.y, a0);
        a0 = fmaf(xa.z, ba.z, a0); a0 = fmaf(xa.w, ba.w, a0);
        a1 = fmaf(xb.x, bb.x, a1); a1 = fmaf(xb.y, bb.y, a1);
        a1 = fmaf(xb.z, bb.z, a1); a1 = fmaf(xb.w, bb.w, a1);
        a2 = fmaf(xc.x, bc.x, a2); a2 = fmaf(xc.y, bc.y, a2);
        a2 = fmaf(xc.z, bc.z, a2); a2 = fmaf(xc.w, bc.w, a2);
        a3 = fmaf(xd.x, bd.x, a3); a3 = fmaf(xd.y, bd.y, a3);
        a3 = fmaf(xd.z, bd.z, a3); a3 = fmaf(xd.w, bd.w, a3);
    }
    return fmaf(-2.f, (a0 + a1) + (a2 + a3), esq);
}

// ---------------- main ----------------
__global__ void __launch_bounds__(THREADS, 1) vq_main(const float* __restrict__ x,
                                                      const float* __restrict__ e,
                                                      float* __restrict__ out) {
    extern __shared__ __align__(16) unsigned char dsm[];
    const uint32_t sb = smem_u32(dsm);
    float* s_esq = reinterpret_cast<float*>(dsm + ESQ_OFF);
    uint4* s_keys = reinterpret_cast<uint4*>(dsm + KEYS_OFF);  // [0..127] tensor, [128..255] fma
    float* s_xsq = reinterpret_cast<float*>(dsm + XSQ_OFF);
    float* s_dbs = reinterpret_cast<float*>(dsm + DBS_OFF);
    int* s_dbi = reinterpret_cast<int*>(dsm + DBI_OFF);
    int* s_widx = reinterpret_cast<int*>(dsm + WIDX_OFF);

    const int tid = threadIdx.x;
    const int warp = tid >> 5, lane = tid & 31;

    // ---- one-time loads ----
#pragma unroll
    for (int i = 0; i < 22; i++) {  // EH: 5632 x 16B
        int line = tid + i * THREADS;
        CP_ASYNC16(sb + EH_OFF + line * 16, reinterpret_cast<const char*>(g_eh) + line * 16);
    }
#pragma unroll
    for (int i = 0; i < 10; i++) {  // EST: 2560 x 16B
        int line = tid + i * THREADS;
        CP_ASYNC16(sb + EST_OFF + line * 16, reinterpret_cast<const char*>(g_et16) + line * 16);
    }
    CP_ASYNC16(sb + ESQ_OFF + tid * 16, reinterpret_cast<const char*>(g_esq) + tid * 16);
    {
        size_t src0 = (size_t)blockIdx.x * 16384;
#pragma unroll
        for (int i = 0; i < 4; i++) {
            int line = tid + i * THREADS;
            CP_ASYNC16(sb + XS_OFF + line * 16, reinterpret_cast<const char*>(g_xh) + src0 + line * 16);
        }
    }
    CP_COMMIT();
    CP_WAIT0();
    __syncthreads();

    const float emax = sqrtf(__int_as_float(g_emax2_bits));
    const int lc = lane & 7, lm = lane >> 3;
    const uint32_t bA0 = sb + EH_OFF + (lc * 64 + ((lm ^ lc) * 8)) * 2;
    const uint32_t bB0 = sb + EH_OFF + (lc * 64 + (((lm + 4) ^ lc) * 8)) * 2;
    const int gcl = 2 * (lane & 3);

    int buf = 0;
    for (int tile = blockIdx.x; tile < NTILES; tile += GRID_MAIN, buf ^= 1) {
        const int row0 = tile * ROWS;
        const uint32_t xs = sb + XS_OFF + buf * 16384;

        CP_WAIT0();
        __syncthreads();  // XS[buf] ready

        // ---- build fp32 k-major XS32 from fp16 XS[buf] (all threads) ----
#pragma unroll
        for (int i = 0; i < 4; i++) {
            int idx = tid + i * THREADS;  // 1024 (g,r) cells
            int g = idx >> 7, r = idx & 127;
            int slot = g ^ (r & 7);
            uint4 pk = *reinterpret_cast<const uint4*>(dsm + XS_OFF + buf * 16384 + r * 128 + slot * 16);
            __half2 h[4];
            memcpy(h, &pk, 16);
#pragma unroll
            for (int j2 = 0; j2 < 4; j2++) {
                float2 f = __half22float2(h[j2]);
                int k0 = g * 8 + j2 * 2;
#pragma unroll
                for (int jj = 0; jj < 2; jj++) {
                    int k = k0 + jj;
                    uint32_t w = (uint32_t)(k * 128 + (((r >> 3) ^ ((k >> 2) & 3)) << 3) + (r & 7));
                    reinterpret_cast<float*>(dsm + XS32_OFF)[w] = jj ? f.y : f.x;
                }
            }
        }

        // ---- tensor warps: A fragments + per-row xsq publish ----
        uint32_t A0[4][4], A1[4][4];
        float xq0 = 0.f, xq1 = 0.f, xq2 = 0.f, xq3 = 0.f;
        if (warp < 4) {
            const int rg = warp;
#pragma unroll
            for (int ks = 0; ks < 4; ks++) {
                int g = 2 * ks + (lane >> 4);
                int r0 = rg * 32 + (lane & 15);
                int r1 = r0 + 16;
                LDSM_X4(A0[ks][0], A0[ks][1], A0[ks][2], A0[ks][3],
                        xs + (r0 * 64 + ((g ^ (r0 & 7)) * 8)) * 2);
                LDSM_X4(A1[ks][0], A1[ks][1], A1[ks][2], A1[ks][3],
                        xs + (r1 * 64 + ((g ^ (r1 & 7)) * 8)) * 2);
            }
            float t0 = 0.f, t1 = 0.f, t2 = 0.f, t3 = 0.f;
#pragma unroll
            for (int ks = 0; ks < 4; ks++) {
                float2 f;
                f = __half22float2(*reinterpret_cast<__half2*>(&A0[ks][0]));
                t0 = fmaf(f.x, f.x, t0); t0 = fmaf(f.y, f.y, t0);
                f = __half22float2(*reinterpret_cast<__half2*>(&A0[ks][2]));
                t0 = fmaf(f.x, f.x, t0); t0 = fmaf(f.y, f.y, t0);
                f = __half22float2(*reinterpret_cast<__half2*>(&A0[ks][1]));
                t1 = fmaf(f.x, f.x, t1); t1 = fmaf(f.y, f.y, t1);
                f = __half22float2(*reinterpret_cast<__half2*>(&A0[ks][3]));
                t1 = fmaf(f.x, f.x, t1); t1 = fmaf(f.y, f.y, t1);
                f = __half22float2(*reinterpret_cast<__half2*>(&A1[ks][0]));
                t2 = fmaf(f.x, f.x, t2); t2 = fmaf(f.y, f.y, t2);
                f = __half22float2(*reinterpret_cast<__half2*>(&A1[ks][2]));
                t2 = fmaf(f.x, f.x, t2); t2 = fmaf(f.y, f.y, t2);
                f = __half22float2(*reinterpret_cast<__half2*>(&A1[ks][1]));
                t3 = fmaf(f.x, f.x, t3); t3 = fmaf(f.y, f.y, t3);
                f = __half22float2(*reinterpret_cast<__half2*>(&A1[ks][3]));
                t3 = fmaf(f.x, f.x, t3); t3 = fmaf(f.y, f.y, t3);
            }
            t0 += __shfl_xor_sync(~0u, t0, 1); t0 += __shfl_xor_sync(~0u, t0, 2);
            t1 += __shfl_xor_sync(~0u, t1, 1); t1 += __shfl_xor_sync(~0u, t1, 2);
            t2 += __shfl_xor_sync(~0u, t2, 1); t2 += __shfl_xor_sync(~0u, t2, 2);
            t3 += __shfl_xor_sync(~0u, t3, 1); t3 += __shfl_xor_sync(~0u, t3, 2);
            xq0 = t0; xq1 = t1; xq2 = t2; xq3 = t3;
            if ((lane & 3) == 0) {
                int r = rg * 32 + (lane >> 2);
                s_xsq[r] = t0; s_xsq[r + 8] = t1;
                s_xsq[r + 16] = t2; s_xsq[r + 24] = t3;
            }
        }
        __syncthreads();  // XS32 + s_xsq visible

        // prefetch next fp16 x tile (all threads)
        if (tile + GRID_MAIN < NTILES) {
            size_t srcn = (size_t)(tile + GRID_MAIN) * 16384;
            uint32_t dst = sb + XS_OFF + (buf ^ 1) * 16384;
#pragma unroll
            for (int i = 0; i < 4; i++) {
                int line = tid + i * THREADS;
                CP_ASYNC16(dst + line * 16, reinterpret_cast<const char*>(g_xh) + srcn + line * 16);
            }
            CP_COMMIT();
        }

        if (warp < 4) {
            // ============ tensor path: codes [0, 704) ============
            const int rg = warp;
            uint32_t ka1 = ~0u, ka2 = ~0u, ka3 = ~0u, ka4 = ~0u;
            uint32_t kb1 = ~0u, kb2 = ~0u, kb3 = ~0u, kb4 = ~0u;
            uint32_t kc1 = ~0u, kc2 = ~0u, kc3 = ~0u, kc4 = ~0u;
            uint32_t kd1 = ~0u, kd2 = ~0u, kd3 = ~0u, kd4 = ~0u;
#pragma unroll 4
            for (int nt = 0; nt < NT_TENSOR; nt++) {
                uint32_t b0, b1, b2, b3, b4, b5, b6, b7;
                LDSM_X4(b0, b1, b2, b3, bA0 + nt * 1024);
                LDSM_X4(b4, b5, b6, b7, bB0 + nt * 1024);
                float c0 = 0.f, c1 = 0.f, c2 = 0.f, c3 = 0.f;
                float d0 = 0.f, d1 = 0.f, d2 = 0.f, d3 = 0.f;
                MMA16816(c0, c1, c2, c3, A0[0][0], A0[0][1], A0[0][2], A0[0][3], b0, b1);
                MMA16816(c0, c1, c2, c3, A0[1][0], A0[1][1], A0[1][2], A0[1][3], b2, b3);
                MMA16816(c0, c1, c2, c3, A0[2][0], A0[2][1], A0[2][2], A0[2][3], b4, b5);
                MMA16816(c0, c1, c2, c3, A0[3][0], A0[3][1], A0[3][2], A0[3][3], b6, b7);
                MMA16816(d0, d1, d2, d3, A1[0][0], A1[0][1], A1[0][2], A1[0][3], b0, b1);
                MMA16816(d0, d1, d2, d3, A1[1][0], A1[1][1], A1[1][2], A1[1][3], b2, b3);
                MMA16816(d0, d1, d2, d3, A1[2][0], A1[2][1], A1[2][2], A1[2][3], b4, b5);
                MMA16816(d0, d1, d2, d3, A1[3][0], A1[3][1], A1[3][2], A1[3][3], b6, b7);

                const int gc0 = nt * 8 + gcl;
                const uint32_t pidx = (uint32_t)(gc0 >> 1);
                float2 eq = *reinterpret_cast<const float2*>(s_esq + gc0);
                uint32_t u;
                u = (__float_as_uint(fminf(fmaf(-2.f, c0, xq0 + eq.x),
                                           fmaf(-2.f, c1, xq0 + eq.y))) & 0xFFFFFC00u) | pidx;
                INS4(ka1, ka2, ka3, ka4, u);
                u = (__float_as_uint(fminf(fmaf(-2.f, c2, xq1 + eq.x),
                                           fmaf(-2.f, c3, xq1 + eq.y))) & 0xFFFFFC00u) | pidx;
                INS4(kb1, kb2, kb3, kb4, u);
                u = (__float_as_uint(fminf(fmaf(-2.f, d0, xq2 + eq.x),
                                           fmaf(-2.f, d1, xq2 + eq.y))) & 0xFFFFFC00u) | pidx;
                INS4(kc1, kc2, kc3, kc4, u);
                u = (__float_as_uint(fminf(fmaf(-2.f, d2, xq3 + eq.x),
                                           fmaf(-2.f, d3, xq3 + eq.y))) & 0xFFFFFC00u) | pidx;
                INS4(kd1, kd2, kd3, kd4, u);
            }
#pragma unroll
            for (int m = 1; m <= 2; m <<= 1) {
                uint32_t o1, o2, o3, o4;
                o1 = __shfl_xor_sync(~0u, ka1, m); o2 = __shfl_xor_sync(~0u, ka2, m);
                o3 = __shfl_xor_sync(~0u, ka3, m); o4 = __shfl_xor_sync(~0u, ka4, m);
                INS4(ka1, ka2, ka3, ka4, o1); INS4(ka1, ka2, ka3, ka4, o2);
                INS4(ka1, ka2, ka3, ka4, o3); INS4(ka1, ka2, ka3, ka4, o4);
                o1 = __shfl_xor_sync(~0u, kb1, m); o2 = __shfl_xor_sync(~0u, kb2, m);
                o3 = __shfl_xor_sync(~0u, kb3, m); o4 = __shfl_xor_sync(~0u, kb4, m);
                INS4(kb1, kb2, kb3, kb4, o1); INS4(kb1, kb2, kb3, kb4, o2);
                INS4(kb1, kb2, kb3, kb4, o3); INS4(kb1, kb2, kb3, kb4, o4);
                o1 = __shfl_xor_sync(~0u, kc1, m); o2 = __shfl_xor_sync(~0u, kc2, m);
                o3 = __shfl_xor_sync(~0u, kc3, m); o4 = __shfl_xor_sync(~0u, kc4, m);
                INS4(kc1, kc2, kc3, kc4, o1); INS4(kc1, kc2, kc3, kc4, o2);
                INS4(kc1, kc2, kc3, kc4, o3); INS4(kc1, kc2, kc3, kc4, o4);
                o1 = __shfl_xor_sync(~0u, kd1, m); o2 = __shfl_xor_sync(~0u, kd2, m);
                o3 = __shfl_xor_sync(~0u, kd3, m); o4 = __shfl_xor_sync(~0u, kd4, m);
                INS4(kd1, kd2, kd3, kd4, o1); INS4(kd1, kd2, kd3, kd4, o2);
                INS4(kd1, kd2, kd3, kd4, o3); INS4(kd1, kd2, kd3, kd4, o4);
            }
            if ((lane & 3) == 0) {
                int r = rg * 32 + (lane >> 2);
                s_keys[r] = make_uint4(ka1, ka2, ka3, ka4);
                s_keys[r + 8] = make_uint4(kb1, kb2, kb3, kb4);
                s_keys[r + 16] = make_uint4(kc1, kc2, kc3, kc4);
                s_keys[r + 24] = make_uint4(kd1, kd2, kd3, kd4);
            }
        } else {
            // ============ fma path: codes [704, 1024), microtiled f32x2 ============
            const int rt = lane >> 3, ct = lane & 7;
            const int R = (warp - 4) * 32 + rt * 8;  // first row of this thread's octet
            const int gr = R >> 3;
            float xsqr[8];
#pragma unroll
            for (int i = 0; i < 8; i++) xsqr[i] = s_xsq[R + i];
            uint32_t fk[8][4];
#pragma unroll
            for (int i = 0; i < 8; i++)
#pragma unroll
                for (int q = 0; q < 4; q++) fk[i][q] = ~0u;

            for (int chunk = 0; chunk < FCHUNKS; chunk++) {
                const int cb = CT + chunk * 32 + ct * 4;  // this thread's 4 codes
                uint64_t acc[4][4];
#pragma unroll
                for (int i = 0; i < 4; i++)
#pragma unroll
                    for (int j = 0; j < 4; j++) acc[i][j] = 0ull;

#pragma unroll 8
                for (int k = 0; k < VQ_D; k++) {
                    int gx = gr ^ ((k >> 2) & 3);
                    const unsigned char* xp = dsm + XS32_OFF + k * 512 + gx * 32;
                    ulonglong2 xa = *reinterpret_cast<const ulonglong2*>(xp);
                    ulonglong2 xb = *reinterpret_cast<const ulonglong2*>(xp + 16);
                    uint2 eh = *reinterpret_cast<const uint2*>(
                        dsm + EST_OFF + k * (FC * 2) + (chunk * 32 + ct * 4) * 2);
                    float2 e01 = __half22float2(*reinterpret_cast<__half2*>(&eh.x));
                    float2 e23 = __half22float2(*reinterpret_cast<__half2*>(&eh.y));
                    uint64_t e0, e1, e2, e3;
                    DUP_F32X2(e0, e01.x); DUP_F32X2(e1, e01.y);
                    DUP_F32X2(e2, e23.x); DUP_F32X2(e3, e23.y);
                    FMA_F32X2(acc[0][0], xa.x, e0); FMA_F32X2(acc[0][1], xa.x, e1);
                    FMA_F32X2(acc[0][2], xa.x, e2); FMA_F32X2(acc[0][3], xa.x, e3);
                    FMA_F32X2(acc[1][0], xa.y, e0); FMA_F32X2(acc[1][1], xa.y, e1);
                    FMA_F32X2(acc[1][2], xa.y, e2); FMA_F32X2(acc[1][3], xa.y, e3);
                    FMA_F32X2(acc[2][0], xb.x, e0); FMA_F32X2(acc[2][1], xb.x, e1);
                    FMA_F32X2(acc[2][2], xb.x, e2); FMA_F32X2(acc[2][3], xb.x, e3);
                    FMA_F32X2(acc[3][0], xb.y, e0); FMA_F32X2(acc[3][1], xb.y, e1);
                    FMA_F32X2(acc[3][2], xb.y, e2); FMA_F32X2(acc[3][3], xb.y, e3);
                }

                // epilogue: pair-compressed keys (pairs cb/2, cb/2+1)
                const float eq0 = s_esq[cb], eq1 = s_esq[cb + 1];
                const float eq2 = s_esq[cb + 2], eq3 = s_esq[cb + 3];
                const uint32_t p0 = (uint32_t)(cb >> 1), p1 = p0 + 1;
#pragma unroll
                for (int i = 0; i < 4; i++) {
                    float2 d0 = u64f2(acc[i][0]), d1 = u64f2(acc[i][1]);
                    float2 d2 = u64f2(acc[i][2]), d3 = u64f2(acc[i][3]);
                    float blo = xsqr[2 * i], bhi = xsqr[2 * i + 1];
                    uint32_t u;
                    u = (__float_as_uint(fminf(fmaf(-2.f, d0.x, blo + eq0),
                                               fmaf(-2.f, d1.x, blo + eq1))) & 0xFFFFFC00u) | p0;
                    INS4(fk[2 * i][0], fk[2 * i][1], fk[2 * i][2], fk[2 * i][3], u);
                    u = (__float_as_uint(fminf(fmaf(-2.f, d2.x, blo + eq2),
                                               fmaf(-2.f, d3.x, blo + eq3))) & 0xFFFFFC00u) | p1;
                    INS4(fk[2 * i][0], fk[2 * i][1], fk[2 * i][2], fk[2 * i][3], u);
                    u = (__float_as_uint(fminf(fmaf(-2.f, d0.y, bhi + eq0),
                                               fmaf(-2.f, d1.y, bhi + eq1))) & 0xFFFFFC00u) | p0;
                    INS4(fk[2 * i + 1][0], fk[2 * i + 1][1], fk[2 * i + 1][2], fk[2 * i + 1][3], u);
                    u = (__float_as_uint(fminf(fmaf(-2.f, d2.y, bhi + eq2),
                                               fmaf(-2.f, d3.y, bhi + eq3))) & 0xFFFFFC00u) | p1;
                    INS4(fk[2 * i + 1][0], fk[2 * i + 1][1], fk[2 * i + 1][2], fk[2 * i + 1][3], u);
                }
            }

            // merge across the 8 ct-lanes sharing these rows
#pragma unroll
            for (int m = 1; m <= 4; m <<= 1) {
#pragma unroll
                for (int i = 0; i < 8; i++) {
                    uint32_t o1 = __shfl_xor_sync(~0u, fk[i][0], m);
                    uint32_t o2 = __shfl_xor_sync(~0u, fk[i][1], m);
                    uint32_t o3 = __shfl_xor_sync(~0u, fk[i][2], m);
                    uint32_t o4 = __shfl_xor_sync(~0u, fk[i][3], m);
                    INS4(fk[i][0], fk[i][1], fk[i][2], fk[i][3], o1);
                    INS4(fk[i][0], fk[i][1], fk[i][2], fk[i][3], o2);
                    INS4(fk[i][0], fk[i][1], fk[i][2], fk[i][3], o3);
                    INS4(fk[i][0], fk[i][1], fk[i][2], fk[i][3], o4);
                }
            }
            if (ct == 0) {
#pragma unroll
                for (int i = 0; i < 8; i++)
                    s_keys[128 + R + i] = make_uint4(fk[i][0], fk[i][1], fk[i][2], fk[i][3]);
            }
        }
        __syncthreads();

        // finalize phase 1: two threads per row (even/odd candidate codes)
        {
            const int row = tid & 127;
            const int half = tid >> 7;
            uint4 h0 = s_keys[row], h1 = s_keys[128 + row];
            uint32_t k1 = h0.x, k2 = h0.y, k3 = h0.z, k4 = h0.w;
            INS4(k1, k2, k3, k4, h1.x); INS4(k1, k2, k3, k4, h1.y);
            INS4(k1, k2, k3, k4, h1.z); INS4(k1, k2, k3, k4, h1.w);
            float m1 = __uint_as_float(k1 & 0xFFFFFC00u);
            float m2 = __uint_as_float(k2 & 0xFFFFFC00u);
            float m4 = __uint_as_float(k4 & 0xFFFFFC00u);
            float margin = 0.0022f * sqrtf(s_xsq[row]) * emax + 0.06f;
            int np;
            if (m2 - m1 >= margin) np = 1;
            else if (m4 - m1 >= margin) np = 3;
            else np = 0;
            float bs = FLT_MAX;
            int bi = 0x7fffffff;
            if (np > 0) {
                const float4* xrp =
                    reinterpret_cast<const float4*>(x + (size_t)(row0 + row) * VQ_D);
                uint32_t plist[3] = {k1 & 0x3FFu, k2 & 0x3FFu, k3 & 0x3FFu};
                for (int j = 0; j < np; j++) {
                    int code = 2 * (int)plist[j] + half;
                    float s = exact_score(xrp, e, code, s_esq[code]);
                    if (s < bs || (s == bs && code < bi)) { bs = s; bi = code; }
                }
            }
            s_dbs[tid] = bs;
            s_dbi[tid] = bi;
            if (half == 0) {
                s_widx[row] = 2 * (int)(k1 & 0x3FFu);  // placeholder (flagged rows)
                if (np == 0) {
                    int slot = atomicAdd(&g_flag_count, 1);
                    g_flag_rows[slot] = row0 + row;
                }
            }
        }
        __syncthreads();

        // finalize phase 2: merge halves
        if (tid < ROWS) {
            float b0 = s_dbs[tid], b1 = s_dbs[tid + 128];
            int i0 = s_dbi[tid], i1 = s_dbi[tid + 128];
            if (i0 != 0x7fffffff || i1 != 0x7fffffff)
                s_widx[tid] = (b1 < b0 || (b1 == b0 && i1 < i0)) ? i1 : i0;
        }
        __syncthreads();

        // gather winning embeddings, coalesced writes
#pragma unroll
        for (int i = 0; i < 8; i++) {
            int idx4 = tid + i * THREADS;
            int r = idx4 >> 4, q = idx4 & 15;
            int id = s_widx[r];
            *reinterpret_cast<float4*>(out + (size_t)(row0 + r) * VQ_D + q * 4) =
                *reinterpret_cast<const float4*>(e + (size_t)id * VQ_D + q * 4);
        }
        __syncthreads();
    }
}

// ---------------- fallback: exact fp32 rescan of flagged rows (rare) ----------------
__global__ void __launch_bounds__(256) vq_fallback(const float* __restrict__ x,
                                                   const float* __restrict__ e,
                                                   float* __restrict__ out) {
    __shared__ float se[64][68];
    __shared__ float sq[64];
    const int tid = threadIdx.x;
    const int wid = tid >> 5, lid = tid & 31;
    const int cnt = g_flag_count;

    for (int base = blockIdx.x * 8; base < cnt; base += gridDim.x * 8) {
        const int rown = base + wid;
        const int row = (rown < cnt) ? g_flag_rows[rown] : -1;
        uint64_t xrp[32];
        if (row >= 0) {
            const float2* xp = reinterpret_cast<const float2*>(x + (size_t)row * VQ_D);
#pragma unroll
            for (int i = 0; i < 32; i++) xrp[i] = f2u64(xp[i]);
        }
        float bs = FLT_MAX;
        int bi = 0x7fffffff;
        for (int cb = 0; cb < VQ_K; cb += 64) {
            __syncthreads();
#pragma unroll
            for (int i = 0; i < 4; i++) {
                int idx4 = tid + i * 256;
                int r = idx4 >> 4, q = idx4 & 15;
                *reinterpret_cast<float4*>(&se[r][q * 4]) =
                    *reinterpret_cast<const float4*>(e + (size_t)(cb + r) * VQ_D + q * 4);
            }
            if (tid < 64) sq[tid] = g_esq[cb + tid];
            __syncthreads();
            if (row >= 0) {
#pragma unroll
                for (int j = 0; j < 2; j++) {
                    int c = j * 32 + lid;
                    const ulonglong2* ev = reinterpret_cast<const ulonglong2*>(&se[c][0]);
                    uint64_t a0 = 0, a1 = 0, a2 = 0, a3 = 0;
#pragma unroll
                    for (int i = 0; i < 8; i++) {
                        ulonglong2 ea = ev[2 * i], eb = ev[2 * i + 1];
                        FMA_F32X2(a0, xrp[4 * i + 0], ea.x);
                        FMA_F32X2(a1, xrp[4 * i + 1], ea.y);
                        FMA_F32X2(a2, xrp[4 * i + 2], eb.x);
                        FMA_F32X2(a3, xrp[4 * i + 3], eb.y);
                    }
                    uint64_t s01, s23, st;
                    ADD_F32X2(s01, a0, a1);
                    ADD_F32X2(s23, a2, a3);
                    ADD_F32X2(st, s01, s23);
                    float2 sv = u64f2(st);
                    float s = fmaf(-2.f, sv.x + sv.y, sq[c]);
                    int code = cb + c;
                    if (s < bs) { bs = s; bi = code; }
                }
            }
        }
        if (row >= 0) {
#pragma unroll
            for (int o = 16; o > 0; o >>= 1) {
                float os = __shfl_down_sync(0xFFFFFFFF, bs, o);
                int oi = __shfl_down_sync(0xFFFFFFFF, bi, o);
                if (os < bs || (os == bs && oi < bi)) { bs = os; bi = oi; }
            }
            bi = __shfl_sync(0xFFFFFFFF, bi, 0);
            if (lid < 16)
                *reinterpret_cast<float4*>(out + (size_t)row * VQ_D + lid * 4) =
                    *reinterpret_cast<const float4*>(e + (size_t)bi * VQ_D + lid * 4);
        }
    }
}

extern "C" void kernel_launch(void* const* d_in, const int* in_sizes, int n_in,
                              void* d_out, int out_size) {
    const float* x = (const float*)d_in[0];           // (131072, 64)
    const float* embeddings = (const float*)d_in[1];  // (1024, 64)
    float* out = (float*)d_out;

    cudaFuncSetAttribute(vq_main, cudaFuncAttributeMaxDynamicSharedMemorySize, SMEM_TOTAL);

    vq_prep<<<(VQ_B * 8) / 256, 256>>>(x, embeddings);
    vq_prep_et<<<(VQ_D * FC + 255) / 256, 256>>>(embeddings);
    vq_main<<<GRID_MAIN, THREADS, SMEM_TOTAL>>>(x, embeddings, out);
    vq_fallback<<<1024, 256>>>(x, embeddings, out);
}

// round 14
// speedup vs baseline: 1.9767x; 1.9767x over previous
#include <cuda_runtime.h>
#include <cuda_fp16.h>
#include <cstdint>
#include <cstring>
#include <cfloat>

// VectorQuantizer: B=131072, D=64, K=1024, fp32.
// Persistent-CTA fp16 mma.sync GEMM, codebook resident in smem.
// 8 warps = 4 row-groups (32 rows) x 2 code-halves (512 codes).
// R14 = R8 scan/finalize + direct-from-fp32 A-fragment construction:
//   x is read fp32 into padded smem staging (double-buffered, prefetched a
//   full tile ahead); A fragments built by per-thread loads + cvt using the
//   canonical m16n8k16 layout. No fp16 x prepass, no XS tile, no LDSM for A.

#define VQ_B 131072
#define VQ_K 1024
#define VQ_D 64
#define ROWS 128
#define THREADS 256
#define NTILES (VQ_B / ROWS)   // 1024
#define GRID_MAIN 148
#define STG_PITCH 272          // 256B data + 16B pad (kills LDS bank conflicts)
#define STG_BYTES (ROWS * STG_PITCH)  // 34816

__device__ float g_esq[VQ_K];
__device__ int g_emax2_bits = 0;
__device__ int g_flag_count;
__device__ int g_flag_rows[VQ_B];
__device__ __half g_eh[(size_t)VQ_K * VQ_D];   // fp16 e, granule-swizzled

// Dynamic smem layout (bytes)
#define ES_OFF     0         // full fp16 codebook: 131072
#define STAGE_OFF  131072    // 2 fp32 x-tile buffers * 34816 = 69632
#define ESQ_OFF    200704    // 1024 floats = 4096
#define KEYS_OFF   204800    // [2][128] uint4 = 4096
#define XSQ_OFF    208896    // 128 floats = 512
#define SMEM_TOTAL 209408

// ---------------- PTX helpers ----------------
static __device__ __forceinline__ uint32_t smem_u32(const void* p) {
    uint32_t a;
    asm("{ .reg .u64 t; cvta.to.shared.u64 t, %1; cvt.u32.u64 %0, t; }" : "=r"(a) : "l"(p));
    return a;
}
#define CP_ASYNC16(dst, src) \
    asm volatile("cp.async.cg.shared.global [%0], [%1], 16;" :: "r"(dst), "l"(src) : "memory")
#define CP_COMMIT() asm volatile("cp.async.commit_group;" ::: "memory")
#define CP_WAIT1() asm volatile("cp.async.wait_group 1;" ::: "memory")
#define CP_WAIT0() asm volatile("cp.async.wait_group 0;" ::: "memory")
#define LDSM_X4(r0, r1, r2, r3, a) \
    asm volatile("ldmatrix.sync.aligned.m8n8.x4.shared.b16 {%0,%1,%2,%3}, [%4];" \
                 : "=r"(r0), "=r"(r1), "=r"(r2), "=r"(r3) : "r"(a))
#define MMA16816(c0, c1, c2, c3, a0, a1, a2, a3, b0, b1) \
    asm volatile("mma.sync.aligned.m16n8k16.row.col.f32.f16.f16.f32 " \
                 "{%0,%1,%2,%3}, {%4,%5,%6,%7}, {%8,%9}, {%0,%1,%2,%3};" \
                 : "+f"(c0), "+f"(c1), "+f"(c2), "+f"(c3) \
                 : "r"(a0), "r"(a1), "r"(a2), "r"(a3), "r"(b0), "r"(b1))

// sorted top-4 insert (keys ascending; k1<=k2<=k3<=k4)
#define INS4(k1, k2, k3, k4, u) do { \
    uint32_t _t1 = max(k1, u); k1 = min(k1, u); \
    uint32_t _t2 = max(k2, _t1); k2 = min(k2, _t1); \
    uint32_t _t3 = max(k3, _t2); k3 = min(k3, _t2); \
    k4 = min(k4, _t3); \
} while (0)

// f32x2 packed math (fallback kernel)
#define FMA_F32X2(acc, a, b) asm("fma.rn.f32x2 %0, %1, %2, %0;" : "+l"(acc) : "l"(a), "l"(b))
#define ADD_F32X2(d, a, b) asm("add.rn.f32x2 %0, %1, %2;" : "=l"(d) : "l"(a), "l"(b))
static __device__ __forceinline__ float2 u64f2(uint64_t u) { float2 v; memcpy(&v, &u, 8); return v; }
static __device__ __forceinline__ uint64_t f2u64(float2 v) { uint64_t u; memcpy(&u, &v, 8); return u; }

static __device__ __forceinline__ uint32_t h2pack(float a, float b) {
    __half2 h = __floats2half2_rn(a, b);
    uint32_t u;
    memcpy(&u, &h, 4);
    return u;
}

// ---------------- prologue: e -> fp16 (granule-swizzled) + esq + emax ----------------
// One thread per (code, 8-dim granule): 8192 threads, width-8 shfl reduce for esq.
__global__ void vq_prep_e(const float* __restrict__ e) {
    int t = blockIdx.x * blockDim.x + threadIdx.x;
    if (t == 0) g_flag_count = 0;
    if (t >= VQ_K * 8) return;
    int c = t >> 3, g = t & 7;
    const float4* p = reinterpret_cast<const float4*>(e + (size_t)c * VQ_D + g * 8);
    float4 v0 = p[0], v1 = p[1];
    float s = v0.x * v0.x + v0.y * v0.y + v0.z * v0.z + v0.w * v0.w +
              v1.x * v1.x + v1.y * v1.y + v1.z * v1.z + v1.w * v1.w;
    __half2 h[4] = {__floats2half2_rn(v0.x, v0.y), __floats2half2_rn(v0.z, v0.w),
                    __floats2half2_rn(v1.x, v1.y), __floats2half2_rn(v1.z, v1.w)};
    uint4 pk;
    memcpy(&pk, h, 16);
    int gp = g ^ (c & 7);
    *reinterpret_cast<uint4*>(&g_eh[(size_t)c * VQ_D + gp * 8]) = pk;
    s += __shfl_down_sync(~0u, s, 4, 8);
    s += __shfl_down_sync(~0u, s, 2, 8);
    s += __shfl_down_sync(~0u, s, 1, 8);
    if (g == 0) {
        g_esq[c] = s;
        atomicMax(&g_emax2_bits, __float_as_int(s));
    }
}

// exact fp32 score with 4 split accumulators
static __device__ __forceinline__ float exact_score(const float4* xr, const float* e, int code,
                                                    float esq) {
    const float4* er = reinterpret_cast<const float4*>(e + (size_t)code * VQ_D);
    float a0 = 0.f, a1 = 0.f, a2 = 0.f, a3 = 0.f;
#pragma unroll
    for (int i = 0; i < 16; i += 4) {
        float4 xa = xr[i], ba = er[i];
        float4 xb = xr[i + 1], bb = er[i + 1];
        float4 xc = xr[i + 2], bc = er[i + 2];
        float4 xd = xr[i + 3], bd = er[i + 3];
        a0 = fmaf(xa.x, ba.x, a0); a0 = fmaf(xa.y, ba.y, a0);
        a0 = fmaf(xa.z, ba.z, a0); a0 = fmaf(xa.w, ba.w, a0);
        a1 = fmaf(xb.x, bb.x, a1); a1 = fmaf(xb.y, bb.y, a1);
        a1 = fmaf(xb.z, bb.z, a1); a1 = fmaf(xb.w, bb.w, a1);
        a2 = fmaf(xc.x, bc.x, a2); a2 = fmaf(xc.y, bc.y, a2);
        a2 = fmaf(xc.z, bc.z, a2); a2 = fmaf(xc.w, bc.w, a2);
        a3 = fmaf(xd.x, bd.x, a3); a3 = fmaf(xd.y, bd.y, a3);
        a3 = fmaf(xd.z, bd.z, a3); a3 = fmaf(xd.w, bd.w, a3);
    }
    return fmaf(-2.f, (a0 + a1) + (a2 + a3), esq);
}

// ---------------- main ----------------
__global__ void __launch_bounds__(THREADS, 1) vq_main(const float* __restrict__ x,
                                                      const float* __restrict__ e,
                                                      float* __restrict__ out) {
    extern __shared__ __align__(16) unsigned char dsm[];
    const uint32_t sb = smem_u32(dsm);
    float* s_esq = reinterpret_cast<float*>(dsm + ESQ_OFF);
    uint4* s_keys = reinterpret_cast<uint4*>(dsm + KEYS_OFF);  // [2][128]
    float* s_xsq = reinterpret_cast<float*>(dsm + XSQ_OFF);    // [128]
    __shared__ int s_widx[ROWS];

    const int tid = threadIdx.x;
    const int warp = tid >> 5, lane = tid & 31;
    const int rg = warp & 3;    // row group: 32 rows rg*32..+31
    const int wh = warp >> 2;   // code half: chunks 4*wh..4*wh+3

    // helper: issue the fp32 x-tile copy for `tile` into staging buffer `b`
    auto stage_tile = [&](int tile, int b) {
#pragma unroll
        for (int i = 0; i < 8; i++) {
            int idx = tid + i * THREADS;  // 2048 lines
            int r = idx >> 4, q = idx & 15;
            CP_ASYNC16(sb + STAGE_OFF + b * STG_BYTES + r * STG_PITCH + q * 16,
                       reinterpret_cast<const char*>(x) +
                           ((size_t)tile * ROWS + r) * (VQ_D * 4) + q * 16);
        }
    };

    // ---- group 1: codebook (128KB) + esq + fp32 x tile 0 ----
#pragma unroll
    for (int i = 0; i < 32; i++) {
        int line = tid + i * THREADS;  // 8192 x 16B
        CP_ASYNC16(sb + ES_OFF + line * 16, reinterpret_cast<const char*>(g_eh) + line * 16);
    }
    CP_ASYNC16(sb + ESQ_OFF + tid * 16, reinterpret_cast<const char*>(g_esq) + tid * 16);
    stage_tile(blockIdx.x, 0);
    CP_COMMIT();
    // ---- group 2: fp32 x tile 1 (prefetch) ----
    if (blockIdx.x + GRID_MAIN < NTILES) stage_tile(blockIdx.x + GRID_MAIN, 1);
    CP_COMMIT();

    const float emax = sqrtf(__int_as_float(g_emax2_bits));
    const int lc = lane & 7, lm = lane >> 3;
    const uint32_t bA0 = sb + ES_OFF + (wh * 4) * 16384 + (lc * 64 + ((lm ^ lc) * 8)) * 2;
    const uint32_t bB0 = sb + ES_OFF + (wh * 4) * 16384 + (lc * 64 + (((lm + 4) ^ lc) * 8)) * 2;
    const int gcl = 2 * (lane & 3);

    int buf = 0;
    for (int tile = blockIdx.x; tile < NTILES; tile += GRID_MAIN, buf ^= 1) {
        const int row0 = tile * ROWS;

        CP_WAIT1();       // all groups but the newest done => stg[buf] (+ e/esq on iter 0)
        __syncthreads();  // cross-thread visibility of cp.async data

        // ---- A fragments directly from fp32 staging (canonical m16n8k16 layout) ----
        // A[ks][0]: row = R + lane/4,     k = 16ks + (lane%4)*2 .. +1
        // A[ks][1]: row = R + 8 + lane/4, same k
        // A[ks][2]: row = R + lane/4,     k + 8
        // A[ks][3]: row = R + 8 + lane/4, k + 8
        uint32_t A0[4][4], A1[4][4];
        {
            const unsigned char* stg = dsm + STAGE_OFF + buf * STG_BYTES;
            const int qr = lane >> 2;             // 0..7
            const int kc = (lane & 3) * 2;        // 0,2,4,6
            const int ra = rg * 32 + qr;          // A0 base row
#pragma unroll
            for (int ks = 0; ks < 4; ks++) {
                const int k0 = 16 * ks + kc;
#pragma unroll
                for (int half = 0; half < 2; half++) {  // A0 then A1 (rows +16)
                    uint32_t (*A)[4] = half ? A1 : A0;
                    const int r_lo = ra + half * 16;
                    const int r_hi = r_lo + 8;
                    float2 v0 = *reinterpret_cast<const float2*>(stg + r_lo * STG_PITCH + k0 * 4);
                    float2 v1 = *reinterpret_cast<const float2*>(stg + r_hi * STG_PITCH + k0 * 4);
                    float2 v2 = *reinterpret_cast<const float2*>(stg + r_lo * STG_PITCH + (k0 + 8) * 4);
                    float2 v3 = *reinterpret_cast<const float2*>(stg + r_hi * STG_PITCH + (k0 + 8) * 4);
                    A[ks][0] = h2pack(v0.x, v0.y);
                    A[ks][1] = h2pack(v1.x, v1.y);
                    A[ks][2] = h2pack(v2.x, v2.y);
                    A[ks][3] = h2pack(v3.x, v3.y);
                }
            }
        }
        __syncthreads();  // all reads of stg[buf] done -> safe to overwrite

        // prefetch fp32 tile t+2*GRID into stg[buf] (always commit: uniform group count)
        if (tile + 2 * GRID_MAIN < NTILES) stage_tile(tile + 2 * GRID_MAIN, buf);
        CP_COMMIT();

        // per-row squared norms from A fragments (rows rg*32 + lane/4 + {0,8,16,24})
        float xq0, xq1, xq2, xq3;
        {
            float t0 = 0.f, t1 = 0.f, t2 = 0.f, t3 = 0.f;
#pragma unroll
            for (int ks = 0; ks < 4; ks++) {
                float2 f;
                f = __half22float2(*reinterpret_cast<__half2*>(&A0[ks][0]));
                t0 = fmaf(f.x, f.x, t0); t0 = fmaf(f.y, f.y, t0);
                f = __half22float2(*reinterpret_cast<__half2*>(&A0[ks][2]));
                t0 = fmaf(f.x, f.x, t0); t0 = fmaf(f.y, f.y, t0);
                f = __half22float2(*reinterpret_cast<__half2*>(&A0[ks][1]));
                t1 = fmaf(f.x, f.x, t1); t1 = fmaf(f.y, f.y, t1);
                f = __half22float2(*reinterpret_cast<__half2*>(&A0[ks][3]));
                t1 = fmaf(f.x, f.x, t1); t1 = fmaf(f.y, f.y, t1);
                f = __half22float2(*reinterpret_cast<__half2*>(&A1[ks][0]));
                t2 = fmaf(f.x, f.x, t2); t2 = fmaf(f.y, f.y, t2);
                f = __half22float2(*reinterpret_cast<__half2*>(&A1[ks][2]));
                t2 = fmaf(f.x, f.x, t2); t2 = fmaf(f.y, f.y, t2);
                f = __half22float2(*reinterpret_cast<__half2*>(&A1[ks][1]));
                t3 = fmaf(f.x, f.x, t3); t3 = fmaf(f.y, f.y, t3);
                f = __half22float2(*reinterpret_cast<__half2*>(&A1[ks][3]));
                t3 = fmaf(f.x, f.x, t3); t3 = fmaf(f.y, f.y, t3);
            }
            t0 += __shfl_xor_sync(~0u, t0, 1); t0 += __shfl_xor_sync(~0u, t0, 2);
            t1 += __shfl_xor_sync(~0u, t1, 1); t1 += __shfl_xor_sync(~0u, t1, 2);
            t2 += __shfl_xor_sync(~0u, t2, 1); t2 += __shfl_xor_sync(~0u, t2, 2);
            t3 += __shfl_xor_sync(~0u, t3, 1); t3 += __shfl_xor_sync(~0u, t3, 2);
            xq0 = t0; xq1 = t1; xq2 = t2; xq3 = t3;
        }

        // ---- scan: top-4 pair-key chains for rows +0, +8, +16, +24 (R8 verbatim) ----
        uint32_t ka1 = ~0u, ka2 = ~0u, ka3 = ~0u, ka4 = ~0u;
        uint32_t kb1 = ~0u, kb2 = ~0u, kb3 = ~0u, kb4 = ~0u;
        uint32_t kc1 = ~0u, kc2 = ~0u, kc3 = ~0u, kc4 = ~0u;
        uint32_t kd1 = ~0u, kd2 = ~0u, kd3 = ~0u, kd4 = ~0u;

        for (int ch2 = 0; ch2 < 4; ch2++) {
            const uint32_t bA = bA0 + ch2 * 16384, bB = bB0 + ch2 * 16384;
            const int chbase = (wh * 4 + ch2) * 128;
#pragma unroll 4
            for (int nt = 0; nt < 16; nt++) {
                uint32_t b0, b1, b2, b3, b4, b5, b6, b7;
                LDSM_X4(b0, b1, b2, b3, bA + nt * 1024);
                LDSM_X4(b4, b5, b6, b7, bB + nt * 1024);
                float c0 = 0.f, c1 = 0.f, c2 = 0.f, c3 = 0.f;
                float d0 = 0.f, d1 = 0.f, d2 = 0.f, d3 = 0.f;
                MMA16816(c0, c1, c2, c3, A0[0][0], A0[0][1], A0[0][2], A0[0][3], b0, b1);
                MMA16816(c0, c1, c2, c3, A0[1][0], A0[1][1], A0[1][2], A0[1][3], b2, b3);
                MMA16816(c0, c1, c2, c3, A0[2][0], A0[2][1], A0[2][2], A0[2][3], b4, b5);
                MMA16816(c0, c1, c2, c3, A0[3][0], A0[3][1], A0[3][2], A0[3][3], b6, b7);
                MMA16816(d0, d1, d2, d3, A1[0][0], A1[0][1], A1[0][2], A1[0][3], b0, b1);
                MMA16816(d0, d1, d2, d3, A1[1][0], A1[1][1], A1[1][2], A1[1][3], b2, b3);
                MMA16816(d0, d1, d2, d3, A1[2][0], A1[2][1], A1[2][2], A1[2][3], b4, b5);
                MMA16816(d0, d1, d2, d3, A1[3][0], A1[3][1], A1[3][2], A1[3][3], b6, b7);

                const int gc0 = chbase + nt * 8 + gcl;
                const uint32_t pidx = (uint32_t)(gc0 >> 1);
                float2 eq = *reinterpret_cast<const float2*>(s_esq + gc0);
                uint32_t u;
                u = (__float_as_uint(fminf(fmaf(-2.f, c0, xq0 + eq.x),
                                           fmaf(-2.f, c1, xq0 + eq.y))) & 0xFFFFFC00u) | pidx;
                INS4(ka1, ka2, ka3, ka4, u);
                u = (__float_as_uint(fminf(fmaf(-2.f, c2, xq1 + eq.x),
                                           fmaf(-2.f, c3, xq1 + eq.y))) & 0xFFFFFC00u) | pidx;
                INS4(kb1, kb2, kb3, kb4, u);
                u = (__float_as_uint(fminf(fmaf(-2.f, d0, xq2 + eq.x),
                                           fmaf(-2.f, d1, xq2 + eq.y))) & 0xFFFFFC00u) | pidx;
                INS4(kc1, kc2, kc3, kc4, u);
                u = (__float_as_uint(fminf(fmaf(-2.f, d2, xq3 + eq.x),
                                           fmaf(-2.f, d3, xq3 + eq.y))) & 0xFFFFFC00u) | pidx;
                INS4(kd1, kd2, kd3, kd4, u);
            }
        }

        // merge top-4 lists across the 4 lanes of each row quad
#pragma unroll
        for (int m = 1; m <= 2; m <<= 1) {
            uint32_t o1, o2, o3, o4;
            o1 = __shfl_xor_sync(~0u, ka1, m); o2 = __shfl_xor_sync(~0u, ka2, m);
            o3 = __shfl_xor_sync(~0u, ka3, m); o4 = __shfl_xor_sync(~0u, ka4, m);
            INS4(ka1, ka2, ka3, ka4, o1); INS4(ka1, ka2, ka3, ka4, o2);
            INS4(ka1, ka2, ka3, ka4, o3); INS4(ka1, ka2, ka3, ka4, o4);
            o1 = __shfl_xor_sync(~0u, kb1, m); o2 = __shfl_xor_sync(~0u, kb2, m);
            o3 = __shfl_xor_sync(~0u, kb3, m); o4 = __shfl_xor_sync(~0u, kb4, m);
            INS4(kb1, kb2, kb3, kb4, o1); INS4(kb1, kb2, kb3, kb4, o2);
            INS4(kb1, kb2, kb3, kb4, o3); INS4(kb1, kb2, kb3, kb4, o4);
            o1 = __shfl_xor_sync(~0u, kc1, m); o2 = __shfl_xor_sync(~0u, kc2, m);
            o3 = __shfl_xor_sync(~0u, kc3, m); o4 = __shfl_xor_sync(~0u, kc4, m);
            INS4(kc1, kc2, kc3, kc4, o1); INS4(kc1, kc2, kc3, kc4, o2);
            INS4(kc1, kc2, kc3, kc4, o3); INS4(kc1, kc2, kc3, kc4, o4);
            o1 = __shfl_xor_sync(~0u, kd1, m); o2 = __shfl_xor_sync(~0u, kd2, m);
            o3 = __shfl_xor_sync(~0u, kd3, m); o4 = __shfl_xor_sync(~0u, kd4, m);
            INS4(kd1, kd2, kd3, kd4, o1); INS4(kd1, kd2, kd3, kd4, o2);
            INS4(kd1, kd2, kd3, kd4, o3); INS4(kd1, kd2, kd3, kd4, o4);
        }

        // leaders publish per-half top-4 lists (+ xq from half 0)
        if ((lane & 3) == 0) {
            int r = rg * 32 + (lane >> 2);
            uint4* dst = s_keys + wh * 128;
            dst[r] = make_uint4(ka1, ka2, ka3, ka4);
            dst[r + 8] = make_uint4(kb1, kb2, kb3, kb4);
            dst[r + 16] = make_uint4(kc1, kc2, kc3, kc4);
            dst[r + 24] = make_uint4(kd1, kd2, kd3, kd4);
            if (wh == 0) {
                s_xsq[r] = xq0; s_xsq[r + 8] = xq1;
                s_xsq[r + 16] = xq2; s_xsq[r + 24] = xq3;
            }
        }
        __syncthreads();

        // finalize: one thread per row — merge halves, certify, duel or flag (R8)
        if (tid < ROWS) {
            uint4 h0 = s_keys[tid], h1 = s_keys[128 + tid];
            uint32_t k1 = h0.x, k2 = h0.y, k3 = h0.z, k4 = h0.w;
            INS4(k1, k2, k3, k4, h1.x); INS4(k1, k2, k3, k4, h1.y);
            INS4(k1, k2, k3, k4, h1.z); INS4(k1, k2, k3, k4, h1.w);
            float m1 = __uint_as_float(k1 & 0xFFFFFC00u);
            float m2 = __uint_as_float(k2 & 0xFFFFFC00u);
            float m4 = __uint_as_float(k4 & 0xFFFFFC00u);
            float margin = 0.0022f * sqrtf(s_xsq[tid]) * emax + 0.06f;
            int np;
            if (m2 - m1 >= margin) np = 1;
            else if (m4 - m1 >= margin) np = 3;
            else np = 0;
            int winner = 2 * (int)(k1 & 0x3FFu);  // placeholder if flagged
            if (np > 0) {
                const float4* xr = reinterpret_cast<const float4*>(x + (size_t)(row0 + tid) * VQ_D);
                uint32_t plist[3] = {k1 & 0x3FFu, k2 & 0x3FFu, k3 & 0x3FFu};
                float bs = FLT_MAX;
                int bi = 0x7fffffff;
                for (int j = 0; j < np; j++) {
                    int c0 = 2 * (int)plist[j];
#pragma unroll
                    for (int tt = 0; tt < 2; tt++) {
                        int code = c0 + tt;
                        float s = exact_score(xr, e, code, s_esq[code]);
                        if (s < bs || (s == bs && code < bi)) { bs = s; bi = code; }
                    }
                }
                winner = bi;
            } else {
                int slot = atomicAdd(&g_flag_count, 1);
                g_flag_rows[slot] = row0 + tid;
            }
            s_widx[tid] = winner;
        }
        __syncthreads();

        // gather winning embeddings (fp32 codebook, L2-resident), coalesced writes
#pragma unroll
        for (int i = 0; i < 8; i++) {
            int idx4 = tid + i * THREADS;
            int r = idx4 >> 4, q = idx4 & 15;
            int id = s_widx[r];
            *reinterpret_cast<float4*>(out + (size_t)(row0 + r) * VQ_D + q * 4) =
                *reinterpret_cast<const float4*>(e + (size_t)id * VQ_D + q * 4);
        }
        __syncthreads();
    }
}

// ---------------- fallback: exact fp32 rescan of flagged rows (rare) ----------------
__global__ void __launch_bounds__(256) vq_fallback(const float* __restrict__ x,
                                                   const float* __restrict__ e,
                                                   float* __restrict__ out) {
    __shared__ float se[64][68];
    __shared__ float sq[64];
    const int tid = threadIdx.x;
    const int wid = tid >> 5, lid = tid & 31;
    const int cnt = g_flag_count;

    for (int base = blockIdx.x * 8; base < cnt; base += gridDim.x * 8) {
        const int rown = base + wid;
        const int row = (rown < cnt) ? g_flag_rows[rown] : -1;
        uint64_t xrp[32];
        if (row >= 0) {
            const float2* xp = reinterpret_cast<const float2*>(x + (size_t)row * VQ_D);
#pragma unroll
            for (int i = 0; i < 32; i++) xrp[i] = f2u64(xp[i]);
        }
        float bs = FLT_MAX;
        int bi = 0x7fffffff;
        for (int cb = 0; cb < VQ_K; cb += 64) {
            __syncthreads();
#pragma unroll
            for (int i = 0; i < 4; i++) {
                int idx4 = tid + i * 256;
                int r = idx4 >> 4, q = idx4 & 15;
                *reinterpret_cast<float4*>(&se[r][q * 4]) =
                    *reinterpret_cast<const float4*>(e + (size_t)(cb + r) * VQ_D + q * 4);
            }
            if (tid < 64) sq[tid] = g_esq[cb + tid];
            __syncthreads();
            if (row >= 0) {
#pragma unroll
                for (int j = 0; j < 2; j++) {
                    int c = j * 32 + lid;
                    const ulonglong2* ev = reinterpret_cast<const ulonglong2*>(&se[c][0]);
                    uint64_t a0 = 0, a1 = 0, a2 = 0, a3 = 0;
#pragma unroll
                    for (int i = 0; i < 8; i++) {
                        ulonglong2 ea = ev[2 * i], eb = ev[2 * i + 1];
                        FMA_F32X2(a0, xrp[4 * i + 0], ea.x);
                        FMA_F32X2(a1, xrp[4 * i + 1], ea.y);
                        FMA_F32X2(a2, xrp[4 * i + 2], eb.x);
                        FMA_F32X2(a3, xrp[4 * i + 3], eb.y);
                    }
                    uint64_t s01, s23, st;
                    ADD_F32X2(s01, a0, a1);
                    ADD_F32X2(s23, a2, a3);
                    ADD_F32X2(st, s01, s23);
                    float2 sv = u64f2(st);
                    float s = fmaf(-2.f, sv.x + sv.y, sq[c]);
                    int code = cb + c;
                    if (s < bs) { bs = s; bi = code; }
                }
            }
        }
        if (row >= 0) {
#pragma unroll
            for (int o = 16; o > 0; o >>= 1) {
                float os = __shfl_down_sync(0xFFFFFFFF, bs, o);
                int oi = __shfl_down_sync(0xFFFFFFFF, bi, o);
                if (os < bs || (os == bs && oi < bi)) { bs = os; bi = oi; }
            }
            bi = __shfl_sync(0xFFFFFFFF, bi, 0);
            if (lid < 16)
                *reinterpret_cast<float4*>(out + (size_t)row * VQ_D + lid * 4) =
                    *reinterpret_cast<const float4*>(e + (size_t)bi * VQ_D + lid * 4);
        }
    }
}

extern "C" void kernel_launch(void* const* d_in, const int* in_sizes, int n_in,
                              void* d_out, int out_size) {
    const float* x = (const float*)d_in[0];           // (131072, 64)
    const float* embeddings = (const float*)d_in[1];  // (1024, 64)
    float* out = (float*)d_out;

    cudaFuncSetAttribute(vq_main, cudaFuncAttributeMaxDynamicSharedMemorySize, SMEM_TOTAL);

    vq_prep_e<<<(VQ_K * 8) / 256, 256>>>(embeddings);
    vq_main<<<GRID_MAIN, THREADS, SMEM_TOTAL>>>(x, embeddings, out);
    vq_fallback<<<1024, 256>>>(x, embeddings, out);
}